// round 12
// baseline (speedup 1.0000x reference)
#include <cuda_runtime.h>
#include <cstdint>

#define TT 8192
#define DD 2048

typedef unsigned long long ull;

// ---------------- device scratch (no allocations allowed) ----------------
__device__ float g_pre[(size_t)TT * DD];        // 64 MB: pre = x @ W1^T + b1
__device__ float g_hs[(size_t)(TT + 1) * DD];   // 64 MB: h per step; sign bit = not-ready

// ---------------- packed f32x2 helpers ----------------
__device__ __forceinline__ ull pk(float lo, float hi) {
    ull r;
    asm("mov.b64 %0, {%1, %2};" : "=l"(r) : "f"(lo), "f"(hi));
    return r;
}
__device__ __forceinline__ void upk(ull v, float& lo, float& hi) {
    asm("mov.b64 {%0, %1}, %2;" : "=f"(lo), "=f"(hi) : "l"(v));
}
__device__ __forceinline__ void fma2(ull& d, ull a, ull b) {
    asm("fma.rn.f32x2 %0, %1, %2, %0;" : "+l"(d) : "l"(a), "l"(b));
}

// ---------------- volatile ld/st (morally strong, guaranteed fresh+live) ----------
__device__ __forceinline__ uint4 ldvol_v4(const float* p) {
    uint4 v;
    asm volatile("ld.volatile.global.v4.u32 {%0,%1,%2,%3}, [%4];"
                 : "=r"(v.x), "=r"(v.y), "=r"(v.z), "=r"(v.w) : "l"(p));
    return v;
}
__device__ __forceinline__ void stvol_f32(float* p, float v) {
    asm volatile("st.volatile.global.f32 [%0], %1;" :: "l"(p), "f"(v));
}

// ---------------- poison kernel: set sign bits (= not ready) everywhere ----------
__global__ void poison_kernel() {
    uint4 p = make_uint4(0xFFFFFFFFu, 0xFFFFFFFFu, 0xFFFFFFFFu, 0xFFFFFFFFu);
    size_t n = (size_t)(TT + 1) * DD / 4;
    uint4* dst = (uint4*)g_hs;
    for (size_t i = (size_t)blockIdx.x * blockDim.x + threadIdx.x; i < n;
         i += (size_t)gridDim.x * blockDim.x)
        dst[i] = p;
}

// ---------------- GEMM: g_pre[t][n] = sum_k x[t][k] * W1[n][k] + b1[n] ----------------
#define BM 128
#define BN 128
#define BK 16
#define LDP 132

__global__ __launch_bounds__(256, 2) void gemm_kernel(
    const float* __restrict__ A,      // x  (TT x DD)
    const float* __restrict__ B,      // W1 (DD x DD), computing A @ B^T
    const float* __restrict__ bias)   // b1
{
    __shared__ __align__(16) float As[BK][LDP];
    __shared__ __align__(16) float Bs[BK][LDP];

    const int tid = threadIdx.x;
    const int m0 = blockIdx.y * BM;
    const int n0 = blockIdx.x * BN;
    const int tx = tid & 15;
    const int ty = tid >> 4;

    ull acc[8][4];
#pragma unroll
    for (int r = 0; r < 8; r++)
#pragma unroll
        for (int c = 0; c < 4; c++) acc[r][c] = 0ull;

    for (int k0 = 0; k0 < DD; k0 += BK) {
#pragma unroll
        for (int i = 0; i < 2; i++) {
            int id = tid + i * 256;
            int r = id >> 2;
            int c = (id & 3) * 4;
            float4 va = *(const float4*)(A + (size_t)(m0 + r) * DD + k0 + c);
            As[c + 0][r] = va.x; As[c + 1][r] = va.y;
            As[c + 2][r] = va.z; As[c + 3][r] = va.w;
            float4 vb = *(const float4*)(B + (size_t)(n0 + r) * DD + k0 + c);
            Bs[c + 0][r] = vb.x; Bs[c + 1][r] = vb.y;
            Bs[c + 2][r] = vb.z; Bs[c + 3][r] = vb.w;
        }
        __syncthreads();

#pragma unroll
        for (int k = 0; k < BK; k++) {
            float4 a0 = *(const float4*)&As[k][ty * 8];
            float4 a1 = *(const float4*)&As[k][ty * 8 + 4];
            ulonglong2 bq0 = *(const ulonglong2*)&Bs[k][tx * 8];
            ulonglong2 bq1 = *(const ulonglong2*)&Bs[k][tx * 8 + 4];
            ull bp0 = bq0.x, bp1 = bq0.y, bp2 = bq1.x, bp3 = bq1.y;
            float ar[8] = {a0.x, a0.y, a0.z, a0.w, a1.x, a1.y, a1.z, a1.w};
#pragma unroll
            for (int r = 0; r < 8; r++) {
                ull ad = pk(ar[r], ar[r]);
                fma2(acc[r][0], ad, bp0);
                fma2(acc[r][1], ad, bp1);
                fma2(acc[r][2], ad, bp2);
                fma2(acc[r][3], ad, bp3);
            }
        }
        __syncthreads();
    }

#pragma unroll
    for (int c = 0; c < 4; c++) {
        int n = n0 + tx * 8 + c * 2;
        float blo = bias[n], bhi = bias[n + 1];
#pragma unroll
        for (int r = 0; r < 8; r++) {
            float lo, hi;
            upk(acc[r][c], lo, hi);
            int m = m0 + ty * 8 + r;
            *(float2*)(g_pre + (size_t)m * DD + n) = make_float2(lo + blo, hi + bhi);
        }
    }
}

// ---------------- persistent scan kernel (sign-bit dataflow sync, zero SHFL) ------
#define NCTA 128
#define NTH  512
#define ROWS 16   // DD / NCTA rows per CTA; warp w owns row blk*16+w
// thread t owns k-chunk [4t, 4t+4)

__global__ __launch_bounds__(NTH, 1) void scan_kernel(
    const float* __restrict__ h0,
    const float* __restrict__ W2,
    const float* __restrict__ b2)
{
    __shared__ __align__(16) float s_part[ROWS * NTH];  // 32 KB stage-1 partials
    __shared__ __align__(16) float s_red[ROWS * 32];    // 2 KB  stage-2 partials

    const int tid  = threadIdx.x;
    const int blk  = blockIdx.x;
    const int lane = tid & 31;
    const int wid  = tid >> 5;
    const int k0   = tid * 4;

    // register-resident W2 slab: rows [blk*16, blk*16+16), cols [k0, k0+4)
    ull w2r0[ROWS], w2r1[ROWS];
#pragma unroll
    for (int j = 0; j < ROWS; j++) {
        float4 w = *(const float4*)(W2 + (size_t)(blk * ROWS + j) * DD + k0);
        w2r0[j] = pk(w.x, w.y);
        w2r1[j] = pk(w.z, w.w);
    }
    const int myrow = blk * ROWS + wid;
    const float myb2 = b2[myrow];
    float pre_next = __ldg(&g_pre[myrow]);

    for (int t = 0; t < TT; t++) {
        float h0v, h1v, h2v, h3v;
        if (t == 0) {
            // h0 is kernel input: ready by definition (and may be negative)
            float4 hv = *(const float4*)(h0 + k0);
            h0v = hv.x; h1v = hv.y; h2v = hv.z; h3v = hv.w;
        } else {
            // one 16B volatile poll; sign bits are the ready flags
            const float* src = g_hs + (size_t)t * DD + k0;
            uint4 a = ldvol_v4(src);
            while (((a.x | a.y | a.z | a.w) & 0x80000000u) != 0u) {
                __nanosleep(40);
                a = ldvol_v4(src);
            }
            h0v = __uint_as_float(a.x);
            h1v = __uint_as_float(a.y);
            h2v = __uint_as_float(a.z);
            h3v = __uint_as_float(a.w);
        }

        float pre_cur = pre_next;
        if (t + 1 < TT) pre_next = __ldg(&g_pre[(size_t)(t + 1) * DD + myrow]);

        // ---- stage 1: per-thread partials for all 16 CTA rows ----
        ull h01 = pk(h0v, h1v);
        ull h23 = pk(h2v, h3v);
#pragma unroll
        for (int j = 0; j < ROWS; j++) {
            ull acc = 0ull;
            fma2(acc, w2r0[j], h01);
            fma2(acc, w2r1[j], h23);
            float lo, hi;
            upk(acc, lo, hi);
            s_part[j * NTH + tid] = lo + hi;
        }
        __syncthreads();

        // ---- stage 2: warp w folds row w's 512 partials -> 32 (register tree) ----
        {
            const float* rowp = s_part + wid * NTH;
            float4 v0 = *(const float4*)(rowp +   0 + lane * 4);
            float4 v1 = *(const float4*)(rowp + 128 + lane * 4);
            float4 v2 = *(const float4*)(rowp + 256 + lane * 4);
            float4 v3 = *(const float4*)(rowp + 384 + lane * 4);
            float s01 = (v0.x + v0.y) + (v0.z + v0.w);
            float s23 = (v1.x + v1.y) + (v1.z + v1.w);
            float s45 = (v2.x + v2.y) + (v2.z + v2.w);
            float s67 = (v3.x + v3.y) + (v3.z + v3.w);
            s_red[wid * 32 + lane] = (s01 + s23) + (s45 + s67);
        }
        __syncthreads();

        // ---- stage 3: lane 0 of warp w folds its row's 32 values, stores h ----
        if (lane == 0) {
            const float4* q = (const float4*)(s_red + wid * 32);
            float4 q0 = q[0], q1 = q[1], q2 = q[2], q3 = q[3];
            float4 q4 = q[4], q5 = q[5], q6 = q[6], q7 = q[7];
            float a0 = ((q0.x + q0.y) + (q0.z + q0.w)) + ((q1.x + q1.y) + (q1.z + q1.w));
            float a1 = ((q2.x + q2.y) + (q2.z + q2.w)) + ((q3.x + q3.y) + (q3.z + q3.w));
            float a2 = ((q4.x + q4.y) + (q4.z + q4.w)) + ((q5.x + q5.y) + (q5.z + q5.w));
            float a3 = ((q6.x + q6.y) + (q6.z + q6.w)) + ((q7.x + q7.y) + (q7.z + q7.w));
            float s = (a0 + a1) + (a2 + a3);

            float y = fmaxf(s + pre_cur + myb2, 0.f);
            // clear sign bit: no-op on ReLU output, and it IS the ready tag
            y = __uint_as_float(__float_as_uint(y) & 0x7FFFFFFFu);
            stvol_f32(&g_hs[(size_t)(t + 1) * DD + myrow], y);
        }
        // stage-3 reads of s_red precede the next step's BAR1; s_red writes at t+1
        // happen after it -> single-buffered smem is race-free (2 BARs/step).
    }
}

// ---------------- final tiny matvec: out[j] = h . Wf[j] + bf[j] ----------------
__global__ void final_kernel(const float* __restrict__ Wf,
                             const float* __restrict__ bf,
                             float* __restrict__ out)
{
    const int wid = threadIdx.x >> 5;   // 4 warps, one per output row
    const int lane = threadIdx.x & 31;
    const float* h = g_hs + (size_t)TT * DD;
    const float* w = Wf + (size_t)wid * DD;
    float s = 0.f;
#pragma unroll
    for (int i = 0; i < 16; i++) {
        int k = i * 128 + lane * 4;
        float4 hv = *(const float4*)(h + k);
        float4 wv = *(const float4*)(w + k);
        s += hv.x * wv.x + hv.y * wv.y + hv.z * wv.z + hv.w * wv.w;
    }
    for (int off = 16; off; off >>= 1) s += __shfl_xor_sync(0xffffffffu, s, off);
    if (lane == 0) out[wid] = s + bf[wid];
}

// ---------------- launch ----------------
extern "C" void kernel_launch(void* const* d_in, const int* in_sizes, int n_in,
                              void* d_out, int out_size)
{
    const float* x  = (const float*)d_in[0];
    const float* h0 = (const float*)d_in[1];
    const float* W1 = (const float*)d_in[2];
    const float* b1 = (const float*)d_in[3];
    const float* W2 = (const float*)d_in[4];
    const float* b2 = (const float*)d_in[5];
    const float* Wf = (const float*)d_in[6];
    const float* bf = (const float*)d_in[7];
    float* out = (float*)d_out;

    poison_kernel<<<2048, 256>>>();
    gemm_kernel<<<dim3(DD / BN, TT / BM), 256>>>(x, W1, b1);
    scan_kernel<<<NCTA, NTH>>>(h0, W2, b2);
    final_kernel<<<1, 128>>>(Wf, bf, out);
}

// round 14
// speedup vs baseline: 2.2983x; 2.2983x over previous
#include <cuda_runtime.h>
#include <cstdint>

#define TT 8192
#define DD 2048

typedef unsigned long long ull;

// ---------------- device scratch (no allocations allowed) ----------------
__device__ float g_pre[(size_t)TT * DD];        // 64 MB: pre = x @ W1^T + b1
__device__ float g_hs[(size_t)(TT + 1) * DD];   // 64 MB: h per step; sign bit = not-ready
#define TILES_M 64   // TT/128
#define TILES_N 16   // DD/128
__device__ int g_tile_cnt[TILES_M];             // per-m-tile completion counters

// ---------------- packed f32x2 helpers ----------------
__device__ __forceinline__ ull pk(float lo, float hi) {
    ull r;
    asm("mov.b64 %0, {%1, %2};" : "=l"(r) : "f"(lo), "f"(hi));
    return r;
}
__device__ __forceinline__ void upk(ull v, float& lo, float& hi) {
    asm("mov.b64 {%0, %1}, %2;" : "=f"(lo), "=f"(hi) : "l"(v));
}
__device__ __forceinline__ void fma2(ull& d, ull a, ull b) {
    asm("fma.rn.f32x2 %0, %1, %2, %0;" : "+l"(d) : "l"(a), "l"(b));
}

// ---------------- volatile ld/st (morally strong, guaranteed fresh+live) ----------
__device__ __forceinline__ uint4 ldvol_v4(const float* p) {
    uint4 v;
    asm volatile("ld.volatile.global.v4.u32 {%0,%1,%2,%3}, [%4];"
                 : "=r"(v.x), "=r"(v.y), "=r"(v.z), "=r"(v.w) : "l"(p));
    return v;
}
__device__ __forceinline__ void stvol_f32(float* p, float v) {
    asm volatile("st.volatile.global.f32 [%0], %1;" :: "l"(p), "f"(v));
}
__device__ __forceinline__ int ldvol_s32(const int* p) {
    int v;
    asm volatile("ld.volatile.global.s32 %0, [%1];" : "=r"(v) : "l"(p));
    return v;
}

// wait until pre m-tile is fully produced (checked once per 128 steps)
__device__ __forceinline__ void wait_tile(int m) {
    const int* p = g_tile_cnt + m;
    int v = ldvol_s32(p);
    while (v < TILES_N) {
        __nanosleep(100);
        v = ldvol_s32(p);
    }
    __threadfence();   // acquire: order subsequent pre reads after counter observation
}

// ---------------- poison kernel: not-ready sign bits + counter reset ----------
__global__ void poison_kernel() {
    if (blockIdx.x == 0 && threadIdx.x < TILES_M) g_tile_cnt[threadIdx.x] = 0;
    uint4 p = make_uint4(0xFFFFFFFFu, 0xFFFFFFFFu, 0xFFFFFFFFu, 0xFFFFFFFFu);
    size_t n = (size_t)(TT + 1) * DD / 4;
    uint4* dst = (uint4*)g_hs;
    for (size_t i = (size_t)blockIdx.x * blockDim.x + threadIdx.x; i < n;
         i += (size_t)gridDim.x * blockDim.x)
        dst[i] = p;
}

// ---------------- fused persistent kernel: scan CTAs + gemm CTAs ----------------
#define NCTA 128     // scan CTAs
#define NG   20      // gemm CTAs (remaining SMs; 148 total = all wave-1 resident)
#define NTH  512
#define ROWS 16      // DD / NCTA rows per scan CTA; warp w owns row blk*16+w
#define LDP 132      // padded gemm smem row

// ---- gemm part: 512 threads, persistent over tiles in m-major order ----
__device__ void gemm_part(float* smem, const float* __restrict__ A,
                          const float* __restrict__ B,
                          const float* __restrict__ bias, int g)
{
    float* As = smem;              // [16][LDP]
    float* Bs = smem + 16 * LDP;   // [16][LDP]
    const int tid = threadIdx.x;
    const int tx = tid & 31;       // 32 col-threads (4 cols each)
    const int ty = tid >> 5;       // 16 row-threads (8 rows each)
    const int lr = tid >> 2;       // load row 0..127
    const int lc = (tid & 3) * 4;  // load col group

    for (int idx = g; idx < TILES_M * TILES_N; idx += NG) {
        const int m0 = (idx >> 4) * 128;
        const int n0 = (idx & 15) * 128;

        ull acc[8][2];
#pragma unroll
        for (int r = 0; r < 8; r++) { acc[r][0] = 0ull; acc[r][1] = 0ull; }

        for (int k0 = 0; k0 < DD; k0 += 16) {
            float4 va = *(const float4*)(A + (size_t)(m0 + lr) * DD + k0 + lc);
            As[(lc + 0) * LDP + lr] = va.x; As[(lc + 1) * LDP + lr] = va.y;
            As[(lc + 2) * LDP + lr] = va.z; As[(lc + 3) * LDP + lr] = va.w;
            float4 vb = *(const float4*)(B + (size_t)(n0 + lr) * DD + k0 + lc);
            Bs[(lc + 0) * LDP + lr] = vb.x; Bs[(lc + 1) * LDP + lr] = vb.y;
            Bs[(lc + 2) * LDP + lr] = vb.z; Bs[(lc + 3) * LDP + lr] = vb.w;
            __syncthreads();

#pragma unroll
            for (int k = 0; k < 16; k++) {
                float4 a0 = *(const float4*)&As[k * LDP + ty * 8];
                float4 a1 = *(const float4*)&As[k * LDP + ty * 8 + 4];
                ulonglong2 bq = *(const ulonglong2*)&Bs[k * LDP + tx * 4];
                float ar[8] = {a0.x, a0.y, a0.z, a0.w, a1.x, a1.y, a1.z, a1.w};
#pragma unroll
                for (int r = 0; r < 8; r++) {
                    ull ad = pk(ar[r], ar[r]);
                    fma2(acc[r][0], ad, bq.x);
                    fma2(acc[r][1], ad, bq.y);
                }
            }
            __syncthreads();
        }

        // epilogue: bias + store
        float4 bb = *(const float4*)(bias + n0 + tx * 4);
#pragma unroll
        for (int r = 0; r < 8; r++) {
            float c0, c1, c2, c3;
            upk(acc[r][0], c0, c1);
            upk(acc[r][1], c2, c3);
            float4 o = make_float4(c0 + bb.x, c1 + bb.y, c2 + bb.z, c3 + bb.w);
            *(float4*)(g_pre + (size_t)(m0 + ty * 8 + r) * DD + n0 + tx * 4) = o;
        }

        __threadfence();      // release: pre stores visible before counter bump
        __syncthreads();
        if (tid == 0) atomicAdd(&g_tile_cnt[idx >> 4], 1);
        __syncthreads();
    }
}

// ---- scan step body (R9-proven form: scalar partials, 1 BAR, warp reduce) ----
struct StepCtx {
    ull w2r0[ROWS], w2r1[ROWS];
    int tid, lane, wid, myrow;
    float myb2;
};

__device__ __forceinline__ void step_body(
    const StepCtx& c, float* s_buf,
    float h0v, float h1v, float h2v, float h3v,
    float pre_cur, float* hstore)
{
    ull h01 = pk(h0v, h1v);
    ull h23 = pk(h2v, h3v);
#pragma unroll
    for (int j = 0; j < ROWS; j++) {
        ull acc = 0ull;
        fma2(acc, c.w2r0[j], h01);
        fma2(acc, c.w2r1[j], h23);
        float lo, hi;
        upk(acc, lo, hi);
        s_buf[j * NTH + c.tid] = lo + hi;
    }
    __syncthreads();

    const float* rowp = s_buf + c.wid * NTH;
    float s = 0.f;
#pragma unroll
    for (int i = 0; i < 4; i++) {
        float4 v = *(const float4*)(rowp + i * 128 + c.lane * 4);
        s += (v.x + v.y) + (v.z + v.w);
    }
    s += __shfl_xor_sync(0xffffffffu, s, 16);
    s += __shfl_xor_sync(0xffffffffu, s, 8);
    s += __shfl_xor_sync(0xffffffffu, s, 4);
    s += __shfl_xor_sync(0xffffffffu, s, 2);
    s += __shfl_xor_sync(0xffffffffu, s, 1);

    if (c.lane == 0) {
        float y = fmaxf(s + pre_cur + c.myb2, 0.f);
        y = __uint_as_float(__float_as_uint(y) & 0x7FFFFFFFu);  // sign bit = ready tag
        stvol_f32(hstore, y);
    }
    // no trailing barrier: double-buffered s_part + per-step BAR + dataflow poll
}

__global__ __launch_bounds__(NTH, 1) void fused_kernel(
    const float* __restrict__ x,
    const float* __restrict__ h0,
    const float* __restrict__ W1,
    const float* __restrict__ b1,
    const float* __restrict__ W2,
    const float* __restrict__ b2)
{
    extern __shared__ float smem[];   // scan: 2*ROWS*NTH floats (64KB); gemm: 17KB

    if (blockIdx.x >= NCTA) {         // ---- gemm CTAs ----
        gemm_part(smem, x, W1, b1, blockIdx.x - NCTA);
        return;
    }

    // ---- scan CTAs ----
    StepCtx c;
    c.tid  = threadIdx.x;
    c.lane = c.tid & 31;
    c.wid  = c.tid >> 5;
    const int blk = blockIdx.x;
    const int k0  = c.tid * 4;

#pragma unroll
    for (int j = 0; j < ROWS; j++) {
        float4 w = *(const float4*)(W2 + (size_t)(blk * ROWS + j) * DD + k0);
        c.w2r0[j] = pk(w.x, w.y);
        c.w2r1[j] = pk(w.z, w.w);
    }
    c.myrow = blk * ROWS + c.wid;
    c.myb2  = b2[c.myrow];

    wait_tile(0);                               // gate pre[0..127]
    float pre_next = __ldg(&g_pre[c.myrow]);

    // ---- step 0 (h0 is input; no poll, may be negative) ----
    {
        float4 hv = *(const float4*)(h0 + k0);
        float pre_cur = pre_next;
        pre_next = __ldg(&g_pre[(size_t)1 * DD + c.myrow]);
        step_body(c, smem, hv.x, hv.y, hv.z, hv.w, pre_cur,
                  &g_hs[(size_t)1 * DD + c.myrow]);
    }

    // ---- steps 1..TT-1 ----
    for (int t = 1; t < TT; t++) {
        const float* src = g_hs + (size_t)t * DD + k0;
        uint4 a = ldvol_v4(src);
        while (((a.x | a.y | a.z | a.w) & 0x80000000u) != 0u) {
            __nanosleep(40);
            a = ldvol_v4(src);
        }
        float pre_cur = pre_next;
        if (t + 1 < TT) {
            if (((t + 1) & 127) == 0) wait_tile((t + 1) >> 7);  // gate next m-tile
            pre_next = __ldg(&g_pre[(size_t)(t + 1) * DD + c.myrow]);
        }

        step_body(c, smem + (t & 1) * (ROWS * NTH),
                  __uint_as_float(a.x), __uint_as_float(a.y),
                  __uint_as_float(a.z), __uint_as_float(a.w),
                  pre_cur, &g_hs[(size_t)(t + 1) * DD + c.myrow]);
    }
}

// ---------------- final tiny matvec: out[j] = h . Wf[j] + bf[j] ----------------
__global__ void final_kernel(const float* __restrict__ Wf,
                             const float* __restrict__ bf,
                             float* __restrict__ out)
{
    const int wid = threadIdx.x >> 5;   // 4 warps, one per output row
    const int lane = threadIdx.x & 31;
    const float* h = g_hs + (size_t)TT * DD;
    const float* w = Wf + (size_t)wid * DD;
    float s = 0.f;
#pragma unroll
    for (int i = 0; i < 16; i++) {
        int k = i * 128 + lane * 4;
        float4 hv = *(const float4*)(h + k);
        float4 wv = *(const float4*)(w + k);
        s += hv.x * wv.x + hv.y * wv.y + hv.z * wv.z + hv.w * wv.w;
    }
    for (int off = 16; off; off >>= 1) s += __shfl_xor_sync(0xffffffffu, s, off);
    if (lane == 0) out[wid] = s + bf[wid];
}

// ---------------- launch ----------------
extern "C" void kernel_launch(void* const* d_in, const int* in_sizes, int n_in,
                              void* d_out, int out_size)
{
    const float* x  = (const float*)d_in[0];
    const float* h0 = (const float*)d_in[1];
    const float* W1 = (const float*)d_in[2];
    const float* b1 = (const float*)d_in[3];
    const float* W2 = (const float*)d_in[4];
    const float* b2 = (const float*)d_in[5];
    const float* Wf = (const float*)d_in[6];
    const float* bf = (const float*)d_in[7];
    float* out = (float*)d_out;

    const int smem_bytes = 2 * ROWS * NTH * (int)sizeof(float);   // 64 KB
    cudaFuncSetAttribute(fused_kernel, cudaFuncAttributeMaxDynamicSharedMemorySize,
                         smem_bytes);

    poison_kernel<<<2048, 256>>>();
    fused_kernel<<<NCTA + NG, NTH, smem_bytes>>>(x, h0, W1, b1, W2, b2);
    final_kernel<<<1, 128>>>(Wf, bf, out);
}